// round 4
// baseline (speedup 1.0000x reference)
#include <cuda_runtime.h>
#include <math.h>

#define NQ  8
#define DIM 256
#define NPAIRS 28

__device__ float2 g_psi[DIM];

__device__ __forceinline__ float2 cmul(float2 a, float2 b) {
    return make_float2(a.x * b.x - a.y * b.y, a.x * b.y + a.y * b.x);
}
__device__ __forceinline__ float2 cadd(float2 a, float2 b) {
    return make_float2(a.x + b.x, a.y + b.y);
}

struct M4 { float2 m[4][4]; };

// ---------------------------------------------------------------------------
// One thread per amplitude. Read old state, sync, write new, sync.
// ---------------------------------------------------------------------------
__device__ __forceinline__ void apply1(float2* s, int b,
                                       float2 u00, float2 u01,
                                       float2 u10, float2 u11) {
    const int tid = threadIdx.x;
    const int m = 1 << b;
    const float2 a0 = s[tid & ~m];
    const float2 a1 = s[tid |  m];
    float2 r;
    if (tid & m) r = cadd(cmul(u10, a0), cmul(u11, a1));
    else         r = cadd(cmul(u00, a0), cmul(u01, a1));
    __syncthreads();
    s[tid] = r;
    __syncthreads();
}

// bH = bit of FIRST wire (matrix high index), bL = bit of SECOND wire.
__device__ __forceinline__ void apply2(float2* s, int bH, int bL, const M4& M) {
    const int tid = threadIdx.x;
    const int mH = 1 << bH, mL = 1 << bL;
    const int base = tid & ~(mH | mL);
    const float2 a0 = s[base];
    const float2 a1 = s[base | mL];
    const float2 a2 = s[base | mH];
    const float2 a3 = s[base | mH | mL];
    const int row = ((tid & mH) ? 2 : 0) + ((tid & mL) ? 1 : 0);
    float2 r =       cmul(M.m[row][0], a0);
    r = cadd(r, cmul(M.m[row][1], a1));
    r = cadd(r, cmul(M.m[row][2], a2));
    r = cadd(r, cmul(M.m[row][3], a3));
    __syncthreads();
    s[tid] = r;
    __syncthreads();
}

__device__ __forceinline__ void rx_g(float2* s, int b, float t) {
    float sn, c; sincosf(0.5f * t, &sn, &c);
    apply1(s, b, make_float2(c, 0.f),  make_float2(0.f, -sn),
                 make_float2(0.f, -sn), make_float2(c, 0.f));
}
__device__ __forceinline__ void ry_g(float2* s, int b, float t) {
    float sn, c; sincosf(0.5f * t, &sn, &c);
    apply1(s, b, make_float2(c, 0.f),  make_float2(-sn, 0.f),
                 make_float2(sn, 0.f), make_float2(c, 0.f));
}
__device__ __forceinline__ void rz_g(float2* s, int b, float t) {
    float sn, c; sincosf(0.5f * t, &sn, &c);
    apply1(s, b, make_float2(c, -sn),  make_float2(0.f, 0.f),
                 make_float2(0.f, 0.f), make_float2(c, sn));
}

__device__ __forceinline__ M4 mat_cnot() {
    M4 M = {};
    M.m[0][0] = make_float2(1.f, 0.f);
    M.m[1][1] = make_float2(1.f, 0.f);
    M.m[2][3] = make_float2(1.f, 0.f);
    M.m[3][2] = make_float2(1.f, 0.f);
    return M;
}
__device__ __forceinline__ M4 mat_ising(float phi) {
    float sn, c; sincosf(0.5f * phi, &sn, &c);
    M4 M = {};
    const float2 C = make_float2(c, 0.f);
    const float2 S = make_float2(0.f, -sn);
    M.m[0][0] = C; M.m[0][3] = S;
    M.m[1][1] = C; M.m[1][2] = S;
    M.m[2][1] = S; M.m[2][2] = C;
    M.m[3][0] = S; M.m[3][3] = C;
    return M;
}

// ---------------------------------------------------------------------------
// Evolve the pure state through the whole circuit. 256 threads.
// ---------------------------------------------------------------------------
__global__ void __launch_bounds__(256, 1)
evolve_kernel(const float* __restrict__ x,
              const float* __restrict__ w,
              const float* __restrict__ cplg) {
    __shared__ float2 s[DIM];
    __shared__ float  sw[210];
    __shared__ float  scpl[64];
    __shared__ float  sq[DIM];
    __shared__ int    pidx[NPAIRS];
    __shared__ float  snorm;

    const int tid = threadIdx.x;
    const float PI_2 = 1.57079632679489662f;

    if (tid < 210) sw[tid]  = w[tid];
    if (tid < 64)  scpl[tid] = cplg[tid];
    const float xv = x[tid];
    sq[tid] = xv * xv;
    __syncthreads();

    if (tid == 0) {
        float acc = 0.f;
        for (int i = 0; i < DIM; i++) acc += sq[i];
        snorm = 1.0f / sqrtf(acc);

        float cmin = scpl[0], cmax = scpl[0];
        for (int i = 1; i < 64; i++) {
            cmin = fminf(cmin, scpl[i]);
            cmax = fmaxf(cmax, scpl[i]);
        }
        const float range = cmax - cmin;
        int count = 0, p = 0;
        for (int i = 0; i < NQ; i++)
            for (int j = i + 1; j < NQ; j++) {
                const bool a = (scpl[i * 8 + j] - cmin) / range > 0.5f;
                pidx[p++] = a ? (3 * NQ + 6 * count) : -1;
                if (a) count++;
            }
    }
    __syncthreads();

    s[tid] = make_float2(xv * snorm, 0.f);
    __syncthreads();

    // per-qubit rx, ry, rz  (wire q acts on flat bit 7-q)
    for (int q = 0; q < NQ; q++) {
        const int b = 7 - q;
        rx_g(s, b, sw[q]);
        ry_g(s, b, sw[q + 8]);
        rz_g(s, b, sw[q + 16]);
    }

    // ising_xx(coupling[i,j]) on wires (i, j) for all pairs
    for (int i = 0; i < NQ; i++)
        for (int j = i + 1; j < NQ; j++)
            apply2(s, 7 - i, 7 - j, mat_ising(scpl[i * 8 + j]));

    // conv + pool on active pairs (block-uniform branch via shared pidx)
    {
        const M4 CN = mat_cnot();
        int p = 0;
        for (int i = 0; i < NQ; i++)
            for (int j = i + 1; j < NQ; j++, p++) {
                const int idx = pidx[p];
                if (idx < 0) continue;
                const int bi = 7 - i;   // wire i
                const int bj = 7 - j;   // wire j
                // conv_block(rho, i, j, p[0:3])
                rz_g(s, bj, -PI_2);
                apply2(s, bj, bi, CN);          // CNOT wires (j, i): control j
                rz_g(s, bi, sw[idx + 0]);
                ry_g(s, bj, sw[idx + 1]);
                apply2(s, bi, bj, CN);          // CNOT wires (i, j): control i
                ry_g(s, bj, sw[idx + 2]);
                apply2(s, bj, bi, CN);
                rz_g(s, bi, PI_2);
                // pool_block(rho, i, j, p[3:6])
                rz_g(s, bj, -PI_2);
                apply2(s, bj, bi, CN);
                rz_g(s, bi, sw[idx + 3]);
                ry_g(s, bj, sw[idx + 4]);
                apply2(s, bi, bj, CN);
                ry_g(s, bj, sw[idx + 5]);
            }
    }

    g_psi[tid] = s[tid];
}

// ---------------------------------------------------------------------------
// Output variants: rho[r][c] = psi[r] * conj(psi[c])
// ---------------------------------------------------------------------------

// (a) real part only: out[r*256+c] = Re(rho[r][c])   (out_size == 65536 floats)
__global__ void __launch_bounds__(256)
outer_real_kernel(float* __restrict__ out) {
    const int r = blockIdx.x;
    const int c = threadIdx.x;
    const float2 a = g_psi[r];
    const float2 b = g_psi[c];
    out[r * DIM + c] = a.x * b.x + a.y * b.y;
}

// (b) planar: out[0:65536] = Re, out[65536:131072] = Im  (out_size == 131072)
__global__ void __launch_bounds__(256)
outer_planar_kernel(float* __restrict__ out) {
    const int r = blockIdx.x;
    const int c = threadIdx.x;
    const float2 a = g_psi[r];
    const float2 b = g_psi[c];
    out[r * DIM + c]             = a.x * b.x + a.y * b.y;
    out[DIM * DIM + r * DIM + c] = a.y * b.x - a.x * b.y;
}

// (c) interleaved complex (fallback; already known-failing at 131072)
__global__ void __launch_bounds__(256)
outer_interleaved_kernel(float2* __restrict__ out) {
    const int r = blockIdx.x;
    const int c = threadIdx.x;
    const float2 a = g_psi[r];
    const float2 b = g_psi[c];
    out[r * DIM + c] = make_float2(a.x * b.x + a.y * b.y,
                                   a.y * b.x - a.x * b.y);
}

extern "C" void kernel_launch(void* const* d_in, const int* in_sizes, int n_in,
                              void* d_out, int out_size) {
    const float* x   = nullptr;
    const float* w   = nullptr;
    const float* cpl = nullptr;
    for (int i = 0; i < n_in; i++) {
        if      (in_sizes[i] == 256) x   = (const float*)d_in[i];
        else if (in_sizes[i] == 210) w   = (const float*)d_in[i];
        else if (in_sizes[i] == 64)  cpl = (const float*)d_in[i];
    }

    evolve_kernel<<<1, 256>>>(x, w, cpl);

    if (out_size == DIM * DIM) {
        // float32 output, 65536 elements -> real part (complex64.astype(float32))
        outer_real_kernel<<<DIM, DIM>>>((float*)d_out);
    } else if (out_size == 2 * DIM * DIM) {
        // 131072 float elements -> planar [Re | Im] (interleaved already falsified)
        outer_planar_kernel<<<DIM, DIM>>>((float*)d_out);
    } else {
        // unknown -> interleaved complex fallback
        outer_interleaved_kernel<<<DIM, DIM>>>((float2*)d_out);
    }
}

// round 5
// speedup vs baseline: 3.1970x; 3.1970x over previous
#include <cuda_runtime.h>

#define NQ  8
#define DIM 256
#define SQ2 0.70710678118654752f

__device__ float2 g_psi[DIM];

__device__ __constant__ unsigned char PI_[28] =
    {0,0,0,0,0,0,0,1,1,1,1,1,1,2,2,2,2,2,3,3,3,3,4,4,4,5,5,6};
__device__ __constant__ unsigned char PJ_[28] =
    {1,2,3,4,5,6,7,2,3,4,5,6,7,3,4,5,6,7,4,5,6,7,5,6,7,6,7,7};

__device__ __forceinline__ float2 cmul(float2 a, float2 b) {
    return make_float2(a.x * b.x - a.y * b.y, a.x * b.y + a.y * b.x);
}
__device__ __forceinline__ float2 cadd(float2 a, float2 b) {
    return make_float2(a.x + b.x, a.y + b.y);
}

// ---------------------------------------------------------------------------
// Evolve kernel: 1 block, 256 threads, one thread per amplitude.
// Ping-pong shared buffers; ONE __syncthreads per gate apply.
// ---------------------------------------------------------------------------
__global__ void __launch_bounds__(256, 1)
evolve_kernel(const float* __restrict__ x,
              const float* __restrict__ w,
              const float* __restrict__ cplg) {
    __shared__ float2 bufA[DIM];
    __shared__ float2 bufB[DIM];
    __shared__ float2 pairM[28][16];   // fused conv+pool 4x4 per pair
    __shared__ float  sw[210];
    __shared__ float  scpl[64];
    __shared__ float  red[8];

    const int tid = threadIdx.x;

    if (tid < 210) sw[tid]   = w[tid];
    if (tid < 64)  scpl[tid] = cplg[tid];
    const float xv = x[tid];

    // block-wide sum of squares (warp shfl + 8 partials)
    float ss = xv * xv;
#pragma unroll
    for (int o = 16; o; o >>= 1) ss += __shfl_xor_sync(0xffffffffu, ss, o);
    if ((tid & 31) == 0) red[tid >> 5] = ss;
    __syncthreads();
    const float inv = rsqrtf(red[0] + red[1] + red[2] + red[3] +
                             red[4] + red[5] + red[6] + red[7]);

    // adjacency bitmask (uniform: every thread computes identically)
    unsigned amask = 0;
    {
        float cmin = scpl[0], cmax = scpl[0];
#pragma unroll 1
        for (int i = 1; i < 64; i++) {
            const float c = scpl[i];
            cmin = fminf(cmin, c);
            cmax = fmaxf(cmax, c);
        }
        const float range = cmax - cmin;
#pragma unroll 1
        for (int p = 0; p < 28; p++) {
            const float cv = scpl[PI_[p] * 8 + PJ_[p]];
            if ((cv - cmin) / range > 0.5f) amask |= 1u << p;
        }
    }

    // ---- build fused conv+pool 4x4 matrices: thread (p*4+col) owns column col
    // of pair p's matrix. Column evolves independently under left-multiplication.
    if (tid < 112) {
        const int p   = tid >> 2;
        const int col = tid & 3;
        const int widx = 3 * NQ + 6 * __popc(amask & ((1u << p) - 1u));

        float2 v0 = make_float2(col == 0 ? 1.f : 0.f, 0.f);
        float2 v1 = make_float2(col == 1 ? 1.f : 0.f, 0.f);
        float2 v2 = make_float2(col == 2 ? 1.f : 0.f, 0.f);
        float2 v3 = make_float2(col == 3 ? 1.f : 0.f, 0.f);

        // helpers as macros over v0..v3; row index = 2*qi + qj
#define PHASE_I(er, ei) { const float2 e = make_float2(er, ei), ec = make_float2(er, -(ei)); \
        v0 = cmul(v0, e); v1 = cmul(v1, e); v2 = cmul(v2, ec); v3 = cmul(v3, ec); }
#define PHASE_J(er, ei) { const float2 e = make_float2(er, ei), ec = make_float2(er, -(ei)); \
        v0 = cmul(v0, e); v1 = cmul(v1, ec); v2 = cmul(v2, e); v3 = cmul(v3, ec); }
#define RY_J(c, s) { float2 t; \
        t  = make_float2((c)*v0.x - (s)*v1.x, (c)*v0.y - (s)*v1.y); \
        v1 = make_float2((s)*v0.x + (c)*v1.x, (s)*v0.y + (c)*v1.y); v0 = t; \
        t  = make_float2((c)*v2.x - (s)*v3.x, (c)*v2.y - (s)*v3.y); \
        v3 = make_float2((s)*v2.x + (c)*v3.x, (s)*v2.y + (c)*v3.y); v2 = t; }
#define SWAP13 { const float2 t = v1; v1 = v3; v3 = t; }
#define SWAP23 { const float2 t = v2; v2 = v3; v3 = t; }

        float s0, c0, s1, c1, s2, c2, s3, c3, s4, c4, s5, c5;
        __sincosf(0.5f * sw[widx + 0], &s0, &c0);
        __sincosf(0.5f * sw[widx + 1], &s1, &c1);
        __sincosf(0.5f * sw[widx + 2], &s2, &c2);
        __sincosf(0.5f * sw[widx + 3], &s3, &c3);
        __sincosf(0.5f * sw[widx + 4], &s4, &c4);
        __sincosf(0.5f * sw[widx + 5], &s5, &c5);

        // conv_block(i, j, p0..p2)
        PHASE_J(SQ2,  SQ2);       // rz(-pi/2) on j
        SWAP13;                   // CNOT(j, i): control j flips qi
        PHASE_I(c0, -s0);         // rz(p0) on i
        RY_J(c1, s1);             // ry(p1) on j
        SWAP23;                   // CNOT(i, j): control i flips qj
        RY_J(c2, s2);             // ry(p2) on j
        SWAP13;                   // CNOT(j, i)
        PHASE_I(SQ2, -SQ2);       // rz(+pi/2) on i
        // pool_block(i, j, p3..p5)
        PHASE_J(SQ2,  SQ2);       // rz(-pi/2) on j
        SWAP13;                   // CNOT(j, i)
        PHASE_I(c3, -s3);         // rz(p3) on i
        RY_J(c4, s4);             // ry(p4) on j
        SWAP23;                   // CNOT(i, j)
        RY_J(c5, s5);             // ry(p5) on j

        pairM[p][0 * 4 + col] = v0;
        pairM[p][1 * 4 + col] = v1;
        pairM[p][2 * 4 + col] = v2;
        pairM[p][3 * 4 + col] = v3;
#undef PHASE_I
#undef PHASE_J
#undef RY_J
#undef SWAP13
#undef SWAP23
    }

    bufA[tid] = make_float2(xv * inv, 0.f);
    __syncthreads();   // covers initial state + pairM

    float2* cur = bufA;
    float2* nxt = bufB;

    // ---- fused single-qubit gates: u = rz(w[q+16]) * ry(w[q+8]) * rx(w[q])
#pragma unroll 1
    for (int q = 0; q < NQ; q++) {
        const int b = 7 - q;
        const int m = 1 << b;
        float sx, cx, sy, cy, sz, cz;
        __sincosf(0.5f * sw[q],      &sx, &cx);
        __sincosf(0.5f * sw[q + 8],  &sy, &cy);
        __sincosf(0.5f * sw[q + 16], &sz, &cz);
        const float2 rx00 = make_float2(cx, 0.f);
        const float2 rx01 = make_float2(0.f, -sx);   // also rx10; rx11 = rx00
        const float2 ry00 = make_float2(cy, 0.f);
        const float2 ry01 = make_float2(-sy, 0.f);
        const float2 ry10 = make_float2(sy, 0.f);
        const float2 ry11 = make_float2(cy, 0.f);
        const float2 m00 = cadd(cmul(ry00, rx00), cmul(ry01, rx01));
        const float2 m01 = cadd(cmul(ry00, rx01), cmul(ry01, rx00));
        const float2 m10 = cadd(cmul(ry10, rx00), cmul(ry11, rx01));
        const float2 m11 = cadd(cmul(ry10, rx01), cmul(ry11, rx00));
        const float2 ez  = make_float2(cz, -sz);
        const float2 ezc = make_float2(cz,  sz);
        const float2 u00 = cmul(ez,  m00);
        const float2 u01 = cmul(ez,  m01);
        const float2 u10 = cmul(ezc, m10);
        const float2 u11 = cmul(ezc, m11);

        const float2 mine = cur[tid];
        const float2 part = cur[tid ^ m];
        const float2 r = (tid & m) ? cadd(cmul(u10, part), cmul(u11, mine))
                                   : cadd(cmul(u00, mine), cmul(u01, part));
        nxt[tid] = r;
        __syncthreads();
        float2* t = cur; cur = nxt; nxt = t;
    }

    // ---- ising_xx butterflies: partner = idx ^ (mi|mj), coeff c, -i*s
#pragma unroll 1
    for (int p = 0; p < 28; p++) {
        const int i = PI_[p], j = PJ_[p];
        const int mask = (1 << (7 - i)) | (1 << (7 - j));
        float s, c;
        __sincosf(0.5f * scpl[i * 8 + j], &s, &c);
        const float2 mine = cur[tid];
        const float2 pv   = cur[tid ^ mask];
        nxt[tid] = make_float2(c * mine.x + s * pv.y,
                               c * mine.y - s * pv.x);
        __syncthreads();
        float2* t = cur; cur = nxt; nxt = t;
    }

    // ---- fused conv+pool applies (uniform predicate)
#pragma unroll 1
    for (int p = 0; p < 28; p++) {
        if ((amask >> p) & 1u) {
            const int bi = 7 - PI_[p];
            const int bj = 7 - PJ_[p];
            const int mi = 1 << bi, mj = 1 << bj;
            const int row  = (((tid >> bi) & 1) << 1) | ((tid >> bj) & 1);
            const int base = tid & ~(mi | mj);
            const float2* Mp = &pairM[p][row * 4];
            float2 r =       cmul(Mp[0], cur[base]);
            r = cadd(r, cmul(Mp[1], cur[base | mj]));
            r = cadd(r, cmul(Mp[2], cur[base | mi]));
            r = cadd(r, cmul(Mp[3], cur[base | mi | mj]));
            nxt[tid] = r;
            __syncthreads();
            float2* t = cur; cur = nxt; nxt = t;
        }
    }

    g_psi[tid] = cur[tid];
}

// ---------------------------------------------------------------------------
// Output: real part of rho[r][c] = psi[r]*conj(psi[c]).
// grid 64, block 256; each thread computes 4 consecutive columns (float4).
// ---------------------------------------------------------------------------
__global__ void __launch_bounds__(256)
outer_real_kernel(float4* __restrict__ out) {
    __shared__ float2 ps[DIM];
    const int tid = threadIdx.x;
    ps[tid] = g_psi[tid];
    __syncthreads();
    const int r  = (blockIdx.x << 2) + (tid >> 6);
    const int c0 = (tid & 63) << 2;
    const float2 a = ps[r];
    const float2 b0 = ps[c0], b1 = ps[c0 + 1], b2 = ps[c0 + 2], b3 = ps[c0 + 3];
    float4 o;
    o.x = a.x * b0.x + a.y * b0.y;
    o.y = a.x * b1.x + a.y * b1.y;
    o.z = a.x * b2.x + a.y * b2.y;
    o.w = a.x * b3.x + a.y * b3.y;
    out[(r << 6) + (tid & 63)] = o;
}

// fallback (unused on this problem; kept for out_size robustness)
__global__ void __launch_bounds__(256)
outer_planar_kernel(float* __restrict__ out) {
    const int r = blockIdx.x;
    const int c = threadIdx.x;
    const float2 a = g_psi[r];
    const float2 b = g_psi[c];
    out[r * DIM + c]             = a.x * b.x + a.y * b.y;
    out[DIM * DIM + r * DIM + c] = a.y * b.x - a.x * b.y;
}

extern "C" void kernel_launch(void* const* d_in, const int* in_sizes, int n_in,
                              void* d_out, int out_size) {
    const float* x   = nullptr;
    const float* w   = nullptr;
    const float* cpl = nullptr;
    for (int i = 0; i < n_in; i++) {
        if      (in_sizes[i] == 256) x   = (const float*)d_in[i];
        else if (in_sizes[i] == 210) w   = (const float*)d_in[i];
        else if (in_sizes[i] == 64)  cpl = (const float*)d_in[i];
    }

    evolve_kernel<<<1, 256>>>(x, w, cpl);

    if (out_size == DIM * DIM) {
        outer_real_kernel<<<64, 256>>>((float4*)d_out);
    } else {
        outer_planar_kernel<<<DIM, DIM>>>((float*)d_out);
    }
}